// round 1
// baseline (speedup 1.0000x reference)
#include <cuda_runtime.h>
#include <cstdint>

// Problem constants
#define NBATCH 8
#define SEQ    4096
#define EMB    512
#define NHEAD  8
#define HDIM   64

// Tiling
#define BM     64      // rows per CTA
#define KC     16      // K-chunk
#define NTHR   256     // 16x16 thread grid, 4x4 outputs per thread per matrix

__device__ __forceinline__ void ffma2(unsigned long long &d,
                                      unsigned long long a,
                                      unsigned long long b) {
    asm("fma.rn.f32x2 %0, %1, %2, %0;" : "+l"(d) : "l"(a), "l"(b));
}
__device__ __forceinline__ unsigned long long dup2(float x) {
    unsigned long long r;
    asm("mov.b64 %0, {%1, %1};" : "=l"(r) : "f"(x));
    return r;
}
__device__ __forceinline__ float lo32(unsigned long long v) { return __uint_as_float((unsigned int)v); }
__device__ __forceinline__ float hi32(unsigned long long v) { return __uint_as_float((unsigned int)(v >> 32)); }

__global__ void __launch_bounds__(NTHR)
fused_attn(const float* __restrict__ Qs, const float* __restrict__ Ks,
           const float* __restrict__ Vs, const int* __restrict__ Qlen,
           const int* __restrict__ Vlen, const float* __restrict__ WQ,
           const float* __restrict__ WK, const float* __restrict__ WV,
           float* __restrict__ out) {
    // X stored as duplicated (x,x) 64-bit words so f32x2 broadcast operand is a single LDS.64.
    // Pad inner dim to 65 to break STS bank conflicts.
    __shared__ unsigned long long sX[3][KC][BM + 1];
    __shared__ float sW[3][KC][HDIM];

    const int h    = blockIdx.x;          // head (fastest -> adjacent CTAs share X rows in L2)
    const int tile = blockIdx.y;          // 64-row tile, 64 tiles per batch
    const int b    = tile >> 6;
    const int s0   = (tile & 63) * BM;
    const int qlen = Qlen[b];
    const int tid  = threadIdx.x;

    float* outbase = out + ((size_t)(b * SEQ + s0)) * EMB + h * HDIM;

    // Entire tile is masked by qmask -> just write zeros (harness poisons d_out).
    if (s0 >= qlen) {
        #pragma unroll
        for (int it = 0; it < (BM * HDIM / 4) / NTHR; it++) {
            int i = it * NTHR + tid;
            int r = i >> 4, c4 = i & 15;
            *(float4*)(outbase + (size_t)r * EMB + c4 * 4) = make_float4(0.f, 0.f, 0.f, 0.f);
        }
        return;
    }

    const int vlen = Vlen[b];
    const int tx = tid & 15, ty = tid >> 4;

    // acc[matrix][row_i][col_pair]: each ull = packed f32x2 (cols 4tx+2p, 4tx+2p+1)
    unsigned long long acc[3][4][2];
    #pragma unroll
    for (int m = 0; m < 3; m++)
        #pragma unroll
        for (int i = 0; i < 4; i++) { acc[m][i][0] = 0ull; acc[m][i][1] = 0ull; }

    const int rl   = tid >> 2, xseg = tid & 3;   // X chunk loader mapping
    const int wrow = tid >> 4, wseg = tid & 15;  // W chunk loader mapping
    const size_t xrow = (size_t)(b * SEQ + s0 + rl) * EMB;

    for (int kk0 = 0; kk0 < EMB; kk0 += KC) {
        __syncthreads();
        #pragma unroll
        for (int m = 0; m < 3; m++) {
            const float* xp = (m == 0) ? Qs : (m == 1) ? Ks : Vs;
            const float* wp = (m == 0) ? WQ : (m == 1) ? WK : WV;
            float4 xv = *(const float4*)(xp + xrow + kk0 + 4 * xseg);
            sX[m][4 * xseg + 0][rl] = dup2(xv.x);
            sX[m][4 * xseg + 1][rl] = dup2(xv.y);
            sX[m][4 * xseg + 2][rl] = dup2(xv.z);
            sX[m][4 * xseg + 3][rl] = dup2(xv.w);
            float4 wv = *(const float4*)(wp + (size_t)(kk0 + wrow) * EMB + h * HDIM + 4 * wseg);
            *(float4*)&sW[m][wrow][4 * wseg] = wv;
        }
        __syncthreads();
        #pragma unroll
        for (int k = 0; k < KC; k++) {
            #pragma unroll
            for (int m = 0; m < 3; m++) {
                ulonglong2 w2 = *(const ulonglong2*)&sW[m][k][4 * tx];
                #pragma unroll
                for (int i = 0; i < 4; i++) {
                    unsigned long long xd = sX[m][k][4 * ty + i];
                    ffma2(acc[m][i][0], xd, w2.x);
                    ffma2(acc[m][i][1], xd, w2.y);
                }
            }
        }
    }

    // Epilogue: per row -> logits, V_len mask (exact ref arithmetic: a - 1e12f),
    // stable softmax over the 64 head cols (16 tx-lanes x 4), times V, times qmask.
    #pragma unroll
    for (int i = 0; i < 4; i++) {
        float qv0 = lo32(acc[0][i][0]), qv1 = hi32(acc[0][i][0]);
        float qv2 = lo32(acc[0][i][1]), qv3 = hi32(acc[0][i][1]);
        float kv0 = lo32(acc[1][i][0]), kv1 = hi32(acc[1][i][0]);
        float kv2 = lo32(acc[1][i][1]), kv3 = hi32(acc[1][i][1]);
        float vv0 = lo32(acc[2][i][0]), vv1 = hi32(acc[2][i][0]);
        float vv2 = lo32(acc[2][i][1]), vv3 = hi32(acc[2][i][1]);

        float l0 = qv0 * kv0 * 0.125f; if (4 * tx + 0 >= vlen) l0 -= 1e12f;
        float l1 = qv1 * kv1 * 0.125f; if (4 * tx + 1 >= vlen) l1 -= 1e12f;
        float l2 = qv2 * kv2 * 0.125f; if (4 * tx + 2 >= vlen) l2 -= 1e12f;
        float l3 = qv3 * kv3 * 0.125f; if (4 * tx + 3 >= vlen) l3 -= 1e12f;

        float mx = fmaxf(fmaxf(l0, l1), fmaxf(l2, l3));
        #pragma unroll
        for (int o = 8; o > 0; o >>= 1)
            mx = fmaxf(mx, __shfl_xor_sync(0xffffffffu, mx, o));

        float e0 = expf(l0 - mx), e1 = expf(l1 - mx);
        float e2 = expf(l2 - mx), e3 = expf(l3 - mx);
        float sum = (e0 + e1) + (e2 + e3);
        #pragma unroll
        for (int o = 8; o > 0; o >>= 1)
            sum += __shfl_xor_sync(0xffffffffu, sum, o);

        float inv = 1.0f / sum;
        float qm = (s0 + 4 * ty + i < qlen) ? 1.0f : 0.0f;
        float4 o4 = make_float4(e0 * inv * vv0 * qm, e1 * inv * vv1 * qm,
                                e2 * inv * vv2 * qm, e3 * inv * vv3 * qm);
        *(float4*)(outbase + (size_t)(4 * ty + i) * EMB + 4 * tx) = o4;
    }
}

extern "C" void kernel_launch(void* const* d_in, const int* in_sizes, int n_in,
                              void* d_out, int out_size) {
    (void)in_sizes; (void)n_in; (void)out_size;
    const float* Qs  = (const float*)d_in[0];
    const float* Ks  = (const float*)d_in[1];
    const float* Vs  = (const float*)d_in[2];
    const int*   Ql  = (const int*)  d_in[3];
    const int*   Vl  = (const int*)  d_in[4];
    const float* WQ  = (const float*)d_in[5];
    const float* WK  = (const float*)d_in[6];
    const float* WV  = (const float*)d_in[7];
    dim3 grid(NHEAD, NBATCH * SEQ / BM);
    fused_attn<<<grid, NTHR>>>(Qs, Ks, Vs, Ql, Vl, WQ, WK, WV, (float*)d_out);
}

// round 3
// speedup vs baseline: 1.8734x; 1.8734x over previous
#include <cuda_runtime.h>
#include <cuda_fp16.h>
#include <cstdint>

// ---------------- scratch (static __device__, no allocs) ----------------
#define XN (3u*32768u*512u)
#define WN (3u*512u*512u)
__device__ __half g_xhi[XN];
__device__ __half g_xlo[XN];
__device__ __half g_wthi[WN];   // [m][n][k] fp16, K-major (W transposed)
__device__ __half g_wtlo[WN];

__device__ __forceinline__ uint32_t smem_u32(const void* p) {
    uint32_t a;
    asm("{ .reg .u64 t; cvta.to.shared.u64 t, %1; cvt.u32.u64 %0, t; }" : "=r"(a) : "l"(p));
    return a;
}

#define LDSM4(r, a) \
    asm volatile("ldmatrix.sync.aligned.m8n8.x4.shared.b16 {%0,%1,%2,%3}, [%4];" \
        : "=r"((r)[0]), "=r"((r)[1]), "=r"((r)[2]), "=r"((r)[3]) : "r"(a))

#define MMA16816(c, a, b0, b1) \
    asm volatile("mma.sync.aligned.m16n8k16.row.col.f32.f16.f16.f32 " \
        "{%0,%1,%2,%3},{%4,%5,%6,%7},{%8,%9},{%0,%1,%2,%3};" \
        : "+f"((c)[0]), "+f"((c)[1]), "+f"((c)[2]), "+f"((c)[3]) \
        : "r"((a)[0]), "r"((a)[1]), "r"((a)[2]), "r"((a)[3]), "r"(b0), "r"(b1))

// ---------------- prep kernels ----------------
__global__ void __launch_bounds__(256)
prep_w(const float* __restrict__ WQ, const float* __restrict__ WK, const float* __restrict__ WV) {
    int idx = blockIdx.x * 256 + threadIdx.x;        // 3*512*512, [m][n][k]
    int m = idx >> 18;
    int r = idx & 262143;
    int n = r >> 9, k = r & 511;
    const float* W = (m == 0) ? WQ : (m == 1) ? WK : WV;
    float x = W[(size_t)k * 512 + n];
    __half h = __float2half_rn(x);
    g_wthi[idx] = h;
    g_wtlo[idx] = __float2half_rn(x - __half2float(h));
}

__global__ void __launch_bounds__(128)
prep_x(const float* __restrict__ Qs, const float* __restrict__ Ks,
       const float* __restrict__ Vs, const int* __restrict__ Qlen) {
    int gid = blockIdx.x;            // 3*32768
    int m = gid >> 15;
    int gr = gid & 32767;
    int b = gr >> 12, s = gr & 4095;
    int qa = (Qlen[b] + 127) & ~127;
    if (s >= qa) return;             // never read by GEMM
    const float* X = (m == 0) ? Qs : (m == 1) ? Ks : Vs;
    float4 v = ((const float4*)(X + ((size_t)gr << 9)))[threadIdx.x];
    union { __half h[4]; uint2 u; } H, L;
    H.h[0] = __float2half_rn(v.x); L.h[0] = __float2half_rn(v.x - __half2float(H.h[0]));
    H.h[1] = __float2half_rn(v.y); L.h[1] = __float2half_rn(v.y - __half2float(H.h[1]));
    H.h[2] = __float2half_rn(v.z); L.h[2] = __float2half_rn(v.z - __half2float(H.h[2]));
    H.h[3] = __float2half_rn(v.w); L.h[3] = __float2half_rn(v.w - __half2float(H.h[3]));
    size_t o = (((size_t)m << 15) + gr) * 512 + threadIdx.x * 4;
    *(uint2*)(g_xhi + o) = H.u;
    *(uint2*)(g_xlo + o) = L.u;
}

// ---------------- fused GEMM (HMMA) + softmax epilogue ----------------
// CTA: 128 rows x 1 head (64 cols). 8 warps, warp tile 32x32.
// K chunks of 32, double-buffered smem. Row stride 40 halfs (80B) -> LDSM conflict-free.
#define KC        32
#define RSTRIDE   80            // bytes per smem row (40 halfs)
#define XSPLIT    10240         // 128*80
#define WOFF      20480
#define WSPLIT    5120          // 64*80
#define MAT_BYTES 30720
#define STAGE_BYTES 92160
#define NCHUNK    16
#define EPI_STRIDE 68           // floats per row in epilogue smem

__global__ void __launch_bounds__(256)
gemm_attn(const int* __restrict__ Qlen, const int* __restrict__ Vlen, float* __restrict__ out) {
    extern __shared__ __align__(16) char dsm[];

    const int h = blockIdx.x;                  // head 0..7 (fastest -> X L2 reuse)
    const int tile = blockIdx.y;               // 0..255
    const int b = tile >> 5;
    const int s0 = (tile & 31) << 7;
    const int tid = threadIdx.x;
    const int qlen = Qlen[b];
    float* outbase = out + ((size_t)(b * 4096 + s0)) * 512 + h * 64;

    if (s0 >= qlen) {                          // whole tile masked: write zeros
        #pragma unroll
        for (int i = 0; i < 8; i++) {
            int lin = tid + i * 256;
            int r = lin >> 4, c4 = lin & 15;
            *(float4*)(outbase + (size_t)r * 512 + c4 * 4) = make_float4(0.f, 0.f, 0.f, 0.f);
        }
        return;
    }

    const uint32_t sbase = smem_u32(dsm);
    const int lane = tid & 31, wid = tid >> 5;
    const int wm = wid >> 1, wn = wid & 1;     // warp tile: rows 32*wm, cols 32*wn

    // ldmatrix lane offsets (bytes)
    const uint32_t aLane = (uint32_t)((wm * 32 + ((lane >> 3) & 1) * 8 + (lane & 7)) * RSTRIDE
                                      + ((lane >> 4) & 1) * 16);
    const uint32_t bLane = (uint32_t)((wn * 32 + ((lane >> 4) & 1) * 8 + (lane & 7)) * RSTRIDE
                                      + ((lane >> 3) & 1) * 16);

    float acc[3][2][4][4];
    #pragma unroll
    for (int m = 0; m < 3; m++)
        #pragma unroll
        for (int mi = 0; mi < 2; mi++)
            #pragma unroll
            for (int nt = 0; nt < 4; nt++)
                #pragma unroll
                for (int q = 0; q < 4; q++) acc[m][mi][nt][q] = 0.f;

    const size_t xrow = (size_t)(b * 4096 + s0);
    const int xr = tid >> 1, xs = tid & 1;     // X loader: row, 32B seg
    const int wr = tid >> 2, ws = tid & 3;     // W loader: row, 16B seg

    auto load_chunk = [&](int c) {
        const int kk0 = c << 5;
        char* sb = dsm + (c & 1) * STAGE_BYTES;
        #pragma unroll
        for (int m = 0; m < 3; m++) {
            const size_t xg = ((size_t)(m << 15) + xrow + xr) * 512 + kk0 + xs * 16;
            const size_t wg = ((size_t)(m * 512 + h * 64 + wr)) * 512 + kk0 + ws * 8;
            uint4 vxh0 = *(const uint4*)(g_xhi + xg);
            uint4 vxh1 = *(const uint4*)(g_xhi + xg + 8);
            uint4 vxl0 = *(const uint4*)(g_xlo + xg);
            uint4 vxl1 = *(const uint4*)(g_xlo + xg + 8);
            uint4 vwh  = *(const uint4*)(g_wthi + wg);
            uint4 vwl  = *(const uint4*)(g_wtlo + wg);
            char* mb = sb + m * MAT_BYTES;
            *(uint4*)(mb + xr * RSTRIDE + xs * 32)          = vxh0;
            *(uint4*)(mb + xr * RSTRIDE + xs * 32 + 16)     = vxh1;
            *(uint4*)(mb + XSPLIT + xr * RSTRIDE + xs * 32)      = vxl0;
            *(uint4*)(mb + XSPLIT + xr * RSTRIDE + xs * 32 + 16) = vxl1;
            *(uint4*)(mb + WOFF + wr * RSTRIDE + ws * 16)           = vwh;
            *(uint4*)(mb + WOFF + WSPLIT + wr * RSTRIDE + ws * 16)  = vwl;
        }
    };

    auto compute = [&](int c) {
        const uint32_t sb = sbase + (c & 1) * STAGE_BYTES;
        #pragma unroll
        for (int ks = 0; ks < 2; ks++) {
            #pragma unroll
            for (int m = 0; m < 3; m++) {
                const uint32_t mb = sb + m * MAT_BYTES + ks * 32;
                uint32_t aH[2][4], aL[2][4], bH[2][4], bL[2][4];
                LDSM4(aH[0], mb + aLane);
                LDSM4(aH[1], mb + aLane + 16 * RSTRIDE);
                LDSM4(aL[0], mb + XSPLIT + aLane);
                LDSM4(aL[1], mb + XSPLIT + aLane + 16 * RSTRIDE);
                LDSM4(bH[0], mb + WOFF + bLane);
                LDSM4(bH[1], mb + WOFF + bLane + 16 * RSTRIDE);
                LDSM4(bL[0], mb + WOFF + WSPLIT + bLane);
                LDSM4(bL[1], mb + WOFF + WSPLIT + bLane + 16 * RSTRIDE);
                #pragma unroll
                for (int mi = 0; mi < 2; mi++)
                    #pragma unroll
                    for (int nt = 0; nt < 4; nt++) {
                        const int nb = nt >> 1, p = (nt & 1) * 2;
                        MMA16816(acc[m][mi][nt], aH[mi], bH[nb][p], bH[nb][p + 1]);
                        MMA16816(acc[m][mi][nt], aH[mi], bL[nb][p], bL[nb][p + 1]);
                        MMA16816(acc[m][mi][nt], aL[mi], bH[nb][p], bH[nb][p + 1]);
                    }
            }
        }
    };

    load_chunk(0);
    __syncthreads();
    for (int c = 0; c < NCHUNK; c++) {
        if (c + 1 < NCHUNK) load_chunk(c + 1);
        compute(c);
        __syncthreads();
    }

    // ---- epilogue: dump accs to smem (reuse tile buffers), per-row softmax ----
    {
        float* sepi = (float*)dsm;
        const int g = lane >> 2, t = lane & 3;
        #pragma unroll
        for (int m = 0; m < 3; m++)
            #pragma unroll
            for (int mi = 0; mi < 2; mi++)
                #pragma unroll
                for (int nt = 0; nt < 4; nt++) {
                    float* p = sepi + (size_t)((m * 128 + wm * 32 + mi * 16 + g) * EPI_STRIDE
                                               + wn * 32 + nt * 8 + 2 * t);
                    p[0] = acc[m][mi][nt][0];
                    p[1] = acc[m][mi][nt][1];
                    p[8 * EPI_STRIDE]     = acc[m][mi][nt][2];
                    p[8 * EPI_STRIDE + 1] = acc[m][mi][nt][3];
                }
        __syncthreads();

        const int row = tid >> 1, hlf = tid & 1;
        const int vlen = Vlen[b];
        float q[32], k[32], v[32];
        #pragma unroll
        for (int j = 0; j < 8; j++) {
            *(float4*)&q[j * 4] = *(float4*)&sepi[(0 * 128 + row) * EPI_STRIDE + hlf * 32 + j * 4];
            *(float4*)&k[j * 4] = *(float4*)&sepi[(1 * 128 + row) * EPI_STRIDE + hlf * 32 + j * 4];
            *(float4*)&v[j * 4] = *(float4*)&sepi[(2 * 128 + row) * EPI_STRIDE + hlf * 32 + j * 4];
        }
        float l[32];
        #pragma unroll
        for (int j = 0; j < 32; j++) {
            l[j] = q[j] * k[j] * 0.125f;
            if (hlf * 32 + j >= vlen) l[j] -= 1e12f;
        }
        float mx = l[0];
        #pragma unroll
        for (int j = 1; j < 32; j++) mx = fmaxf(mx, l[j]);
        mx = fmaxf(mx, __shfl_xor_sync(0xffffffffu, mx, 1));
        float sum = 0.f;
        #pragma unroll
        for (int j = 0; j < 32; j++) { l[j] = expf(l[j] - mx); sum += l[j]; }
        sum += __shfl_xor_sync(0xffffffffu, sum, 1);
        float sc = 1.0f / sum;
        if (s0 + row >= qlen) sc = 0.f;        // qmask
        float* op = outbase + (size_t)row * 512 + hlf * 32;
        #pragma unroll
        for (int j = 0; j < 8; j++) {
            float4 o4 = make_float4(l[j * 4 + 0] * v[j * 4 + 0] * sc,
                                    l[j * 4 + 1] * v[j * 4 + 1] * sc,
                                    l[j * 4 + 2] * v[j * 4 + 2] * sc,
                                    l[j * 4 + 3] * v[j * 4 + 3] * sc);
            *(float4*)(op + j * 4) = o4;
        }
    }
}

// ---------------- launch ----------------
extern "C" void kernel_launch(void* const* d_in, const int* in_sizes, int n_in,
                              void* d_out, int out_size) {
    (void)in_sizes; (void)n_in; (void)out_size;
    const float* Qs = (const float*)d_in[0];
    const float* Ks = (const float*)d_in[1];
    const float* Vs = (const float*)d_in[2];
    const int*   Ql = (const int*)d_in[3];
    const int*   Vl = (const int*)d_in[4];
    const float* WQ = (const float*)d_in[5];
    const float* WK = (const float*)d_in[6];
    const float* WV = (const float*)d_in[7];

    static int smem_set = 0;
    if (!smem_set) {
        cudaFuncSetAttribute(gemm_attn, cudaFuncAttributeMaxDynamicSharedMemorySize,
                             2 * STAGE_BYTES);
        smem_set = 1;
    }

    prep_w<<<3072, 256>>>(WQ, WK, WV);
    prep_x<<<98304, 128>>>(Qs, Ks, Vs, Ql);
    gemm_attn<<<dim3(8, 256), 256, 2 * STAGE_BYTES>>>(Ql, Vl, (float*)d_out);
}

// round 5
// speedup vs baseline: 2.3040x; 1.2298x over previous
#include <cuda_runtime.h>
#include <cuda_fp16.h>
#include <cstdint>

// ---------------- scratch (static __device__, no allocs) ----------------
#define XN (3u*32768u*512u)
#define WN (3u*512u*512u)
__device__ __half g_xhi[XN];
__device__ __half g_xlo[XN];
__device__ __half g_wthi[WN];   // [m][n][k] fp16, K-major (W transposed)
__device__ __half g_wtlo[WN];

__device__ __forceinline__ uint32_t smem_u32(const void* p) {
    uint32_t a;
    asm("{ .reg .u64 t; cvta.to.shared.u64 t, %1; cvt.u32.u64 %0, t; }" : "=r"(a) : "l"(p));
    return a;
}

#define LDSM4(r, a) \
    asm volatile("ldmatrix.sync.aligned.m8n8.x4.shared.b16 {%0,%1,%2,%3}, [%4];" \
        : "=r"((r)[0]), "=r"((r)[1]), "=r"((r)[2]), "=r"((r)[3]) : "r"(a))

#define MMA16816(c, a, b0, b1) \
    asm volatile("mma.sync.aligned.m16n8k16.row.col.f32.f16.f16.f32 " \
        "{%0,%1,%2,%3},{%4,%5,%6,%7},{%8,%9},{%0,%1,%2,%3};" \
        : "+f"((c)[0]), "+f"((c)[1]), "+f"((c)[2]), "+f"((c)[3]) \
        : "r"((a)[0]), "r"((a)[1]), "r"((a)[2]), "r"((a)[3]), "r"(b0), "r"(b1))

#define CPA16(dst, src) \
    asm volatile("cp.async.cg.shared.global [%0], [%1], 16;" :: "r"(dst), "l"(src))
#define CPCOMMIT() asm volatile("cp.async.commit_group;" ::: "memory")
#define CPWAIT(n)  asm volatile("cp.async.wait_group %0;" :: "n"(n) : "memory")

// ---------------- prep kernels ----------------
__global__ void __launch_bounds__(256)
prep_w(const float* __restrict__ WQ, const float* __restrict__ WK, const float* __restrict__ WV) {
    int idx = blockIdx.x * 256 + threadIdx.x;        // 3*512*512, [m][n][k]
    int m = idx >> 18;
    int r = idx & 262143;
    int n = r >> 9, k = r & 511;
    const float* W = (m == 0) ? WQ : (m == 1) ? WK : WV;
    float x = W[(size_t)k * 512 + n];
    __half h = __float2half_rn(x);
    g_wthi[idx] = h;
    g_wtlo[idx] = __float2half_rn(x - __half2float(h));
}

__global__ void __launch_bounds__(128)
prep_x(const float* __restrict__ Qs, const float* __restrict__ Ks,
       const float* __restrict__ Vs, const int* __restrict__ Qlen) {
    int gid = blockIdx.x;            // 3*32768
    int m = gid >> 15;
    int gr = gid & 32767;
    int b = gr >> 12, s = gr & 4095;
    int qa = (Qlen[b] + 127) & ~127;
    if (s >= qa) return;             // never read by GEMM
    const float* X = (m == 0) ? Qs : (m == 1) ? Ks : Vs;
    float4 v = ((const float4*)(X + ((size_t)gr << 9)))[threadIdx.x];
    union { __half h[4]; uint2 u; } H, L;
    H.h[0] = __float2half_rn(v.x); L.h[0] = __float2half_rn(v.x - __half2float(H.h[0]));
    H.h[1] = __float2half_rn(v.y); L.h[1] = __float2half_rn(v.y - __half2float(H.h[1]));
    H.h[2] = __float2half_rn(v.z); L.h[2] = __float2half_rn(v.z - __half2float(H.h[2]));
    H.h[3] = __float2half_rn(v.w); L.h[3] = __float2half_rn(v.w - __half2float(H.h[3]));
    size_t o = (((size_t)m << 15) + gr) * 512 + threadIdx.x * 4;
    *(uint2*)(g_xhi + o) = H.u;
    *(uint2*)(g_xlo + o) = L.u;
}

// ---------------- fused GEMM (HMMA) + softmax epilogue ----------------
// CTA: 64 rows x 1 head (64 cols), 128 threads, 4 warps (warp tile 32x32).
// K chunks of 32, double-buffered cp.async pipeline, 96KB smem -> 2 CTAs/SM.
// Compact swizzled layout: tile = 64 rows x 64B, phys 16B-col = c ^ ((r>>1)&3).
#define TILE_B    4096
#define MAT_B     16384          // Xhi,Xlo,Whi,Wlo
#define STAGE_B   49152          // 3 matrices
#define NCHUNK    16
#define EPI_STRIDE 68            // floats per row in epilogue smem

__global__ void __launch_bounds__(128)
gemm_attn(const int* __restrict__ Qlen, const int* __restrict__ Vlen, float* __restrict__ out) {
    extern __shared__ __align__(16) char dsm[];

    const int h = blockIdx.x;                  // head 0..7 (fastest -> X L2 reuse)
    const int tile = blockIdx.y;               // 0..511
    const int b = tile >> 6;
    const int s0 = (tile & 63) << 6;
    const int tid = threadIdx.x;
    const int qlen = Qlen[b];
    float* outbase = out + ((size_t)(b * 4096 + s0)) * 512 + h * 64;

    if (s0 >= qlen) {                          // whole tile masked: write zeros
        #pragma unroll
        for (int i = 0; i < 8; i++) {
            int lin = tid + i * 128;
            int r = lin >> 4, c4 = lin & 15;
            *(float4*)(outbase + (size_t)r * 512 + c4 * 4) = make_float4(0.f, 0.f, 0.f, 0.f);
        }
        return;
    }

    const uint32_t sbase = smem_u32(dsm);
    const int lane = tid & 31, wid = tid >> 5;
    const int wm = wid >> 1, wn = wid & 1;     // warp tile: rows 32*wm, cols 32*wn

    // ldmatrix logical mapping (same as proven round-3), swizzled physical address
    const int rA = wm * 32 + ((lane >> 3) & 1) * 8 + (lane & 7);
    const int cA = (lane >> 4) & 1;
    const int swA = (rA >> 1) & 3;
    const int rB = wn * 32 + ((lane >> 4) & 1) * 8 + (lane & 7);
    const int cB = (lane >> 3) & 1;
    const int swB = (rB >> 1) & 3;
    uint32_t offA[2], offB[2];
    #pragma unroll
    for (int ks = 0; ks < 2; ks++) {
        offA[ks] = (uint32_t)(rA * 64 + (((ks * 2 + cA) ^ swA) << 4));
        offB[ks] = (uint32_t)(rB * 64 + (((ks * 2 + cB) ^ swB) << 4));
    }

    float acc[3][2][4][4];
    #pragma unroll
    for (int m = 0; m < 3; m++)
        #pragma unroll
        for (int mi = 0; mi < 2; mi++)
            #pragma unroll
            for (int nt = 0; nt < 4; nt++)
                #pragma unroll
                for (int q = 0; q < 4; q++) acc[m][mi][nt][q] = 0.f;

    const size_t xrow = (size_t)(b * 4096 + s0);

    // cp.async loader mapping: thread -> row tid>>1, 2 of 4 16B-cols
    const int lr = tid >> 1;
    const int lc0 = (tid & 1) * 2;
    const uint32_t lsw = (uint32_t)((lr >> 1) & 3);
    const uint32_t lrow = (uint32_t)(lr << 6);

    auto load_stage = [&](int c) {
        const int kk0 = (c & 15) << 5;
        const uint32_t sb = sbase + (c & 1) * STAGE_B;
        #pragma unroll
        for (int m = 0; m < 3; m++) {
            const size_t xg = ((size_t)(m << 15) + xrow + lr) * 512 + kk0;
            const size_t wg = ((size_t)(m * 512 + h * 64 + lr)) * 512 + kk0;
            const uint32_t mb = sb + m * MAT_B;
            #pragma unroll
            for (int j = 0; j < 2; j++) {
                const int cc = lc0 + j;
                const uint32_t po = lrow + (((uint32_t)cc ^ lsw) << 4);
                CPA16(mb + po,                 g_xhi  + xg + cc * 8);
                CPA16(mb + TILE_B + po,        g_xlo  + xg + cc * 8);
                CPA16(mb + 2 * TILE_B + po,    g_wthi + wg + cc * 8);
                CPA16(mb + 3 * TILE_B + po,    g_wtlo + wg + cc * 8);
            }
        }
        CPCOMMIT();
    };

    auto compute = [&](int c) {
        const uint32_t sb = sbase + (c & 1) * STAGE_B;
        #pragma unroll
        for (int ks = 0; ks < 2; ks++) {
            #pragma unroll
            for (int m = 0; m < 3; m++) {
                const uint32_t mb = sb + m * MAT_B;
                uint32_t aH[2][4], aL[2][4], bH[2][4], bL[2][4];
                LDSM4(aH[0], mb + offA[ks]);
                LDSM4(aH[1], mb + offA[ks] + 1024);
                LDSM4(aL[0], mb + TILE_B + offA[ks]);
                LDSM4(aL[1], mb + TILE_B + offA[ks] + 1024);
                LDSM4(bH[0], mb + 2 * TILE_B + offB[ks]);
                LDSM4(bH[1], mb + 2 * TILE_B + offB[ks] + 1024);
                LDSM4(bL[0], mb + 3 * TILE_B + offB[ks]);
                LDSM4(bL[1], mb + 3 * TILE_B + offB[ks] + 1024);
                #pragma unroll
                for (int mi = 0; mi < 2; mi++)
                    #pragma unroll
                    for (int nt = 0; nt < 4; nt++) {
                        const int nb = nt >> 1, p = (nt & 1) * 2;
                        MMA16816(acc[m][mi][nt], aH[mi], bH[nb][p], bH[nb][p + 1]);
                        MMA16816(acc[m][mi][nt], aH[mi], bL[nb][p], bL[nb][p + 1]);
                        MMA16816(acc[m][mi][nt], aL[mi], bH[nb][p], bH[nb][p + 1]);
                    }
            }
        }
    };

    load_stage(0);
    load_stage(1);
    for (int c = 0; c < NCHUNK; c++) {
        if (c < NCHUNK - 1) { CPWAIT(1); } else { CPWAIT(0); }
        __syncthreads();
        compute(c);
        __syncthreads();
        if (c + 2 < NCHUNK) load_stage(c + 2);
    }

    // ---- epilogue: dump accs to smem (reuse tile buffers), per-row softmax ----
    {
        float* sepi = (float*)dsm;
        const int g = lane >> 2, t = lane & 3;
        #pragma unroll
        for (int m = 0; m < 3; m++)
            #pragma unroll
            for (int mi = 0; mi < 2; mi++)
                #pragma unroll
                for (int nt = 0; nt < 4; nt++) {
                    float* p = sepi + (size_t)((m * 64 + wm * 32 + mi * 16 + g) * EPI_STRIDE
                                               + wn * 32 + nt * 8 + 2 * t);
                    p[0] = acc[m][mi][nt][0];
                    p[1] = acc[m][mi][nt][1];
                    p[8 * EPI_STRIDE]     = acc[m][mi][nt][2];
                    p[8 * EPI_STRIDE + 1] = acc[m][mi][nt][3];
                }
        __syncthreads();

        const int row = tid >> 1, hlf = tid & 1;
        const int vlen = Vlen[b];
        float q[32], k[32], v[32];
        #pragma unroll
        for (int j = 0; j < 8; j++) {
            *(float4*)&q[j * 4] = *(float4*)&sepi[(0 * 64 + row) * EPI_STRIDE + hlf * 32 + j * 4];
            *(float4*)&k[j * 4] = *(float4*)&sepi[(1 * 64 + row) * EPI_STRIDE + hlf * 32 + j * 4];
            *(float4*)&v[j * 4] = *(float4*)&sepi[(2 * 64 + row) * EPI_STRIDE + hlf * 32 + j * 4];
        }
        float l[32];
        #pragma unroll
        for (int j = 0; j < 32; j++) {
            l[j] = q[j] * k[j] * 0.125f;
            if (hlf * 32 + j >= vlen) l[j] -= 1e12f;
        }
        float mx = l[0];
        #pragma unroll
        for (int j = 1; j < 32; j++) mx = fmaxf(mx, l[j]);
        mx = fmaxf(mx, __shfl_xor_sync(0xffffffffu, mx, 1));
        float sum = 0.f;
        #pragma unroll
        for (int j = 0; j < 32; j++) { l[j] = expf(l[j] - mx); sum += l[j]; }
        sum += __shfl_xor_sync(0xffffffffu, sum, 1);
        float sc = 1.0f / sum;
        if (s0 + row >= qlen) sc = 0.f;        // qmask
        float* op = outbase + (size_t)row * 512 + hlf * 32;
        #pragma unroll
        for (int j = 0; j < 8; j++) {
            float4 o4 = make_float4(l[j * 4 + 0] * v[j * 4 + 0] * sc,
                                    l[j * 4 + 1] * v[j * 4 + 1] * sc,
                                    l[j * 4 + 2] * v[j * 4 + 2] * sc,
                                    l[j * 4 + 3] * v[j * 4 + 3] * sc);
            *(float4*)(op + j * 4) = o4;
        }
    }
}

// ---------------- launch ----------------
extern "C" void kernel_launch(void* const* d_in, const int* in_sizes, int n_in,
                              void* d_out, int out_size) {
    (void)in_sizes; (void)n_in; (void)out_size;
    const float* Qs = (const float*)d_in[0];
    const float* Ks = (const float*)d_in[1];
    const float* Vs = (const float*)d_in[2];
    const int*   Ql = (const int*)d_in[3];
    const int*   Vl = (const int*)d_in[4];
    const float* WQ = (const float*)d_in[5];
    const float* WK = (const float*)d_in[6];
    const float* WV = (const float*)d_in[7];

    static int smem_set = 0;
    if (!smem_set) {
        cudaFuncSetAttribute(gemm_attn, cudaFuncAttributeMaxDynamicSharedMemorySize,
                             2 * STAGE_B);
        smem_set = 1;
    }

    prep_w<<<3072, 256>>>(WQ, WK, WV);
    prep_x<<<98304, 128>>>(Qs, Ks, Vs, Ql);
    gemm_attn<<<dim3(8, 512), 128, 2 * STAGE_B>>>(Ql, Vl, (float*)d_out);
}

// round 6
// speedup vs baseline: 2.9058x; 1.2612x over previous
#include <cuda_runtime.h>
#include <cuda_fp16.h>
#include <cstdint>

// ---------------- scratch (static __device__, no allocs) ----------------
#define XN (3u*32768u*512u)
#define WN (3u*512u*512u)
__device__ __half g_xhi[XN];
__device__ __half g_xlo[XN];
__device__ __half g_wthi[WN];   // [m][n][k] fp16, K-major (W transposed)
__device__ __half g_wtlo[WN];

__device__ __forceinline__ uint32_t smem_u32(const void* p) {
    uint32_t a;
    asm("{ .reg .u64 t; cvta.to.shared.u64 t, %1; cvt.u32.u64 %0, t; }" : "=r"(a) : "l"(p));
    return a;
}

#define LDSM4(r, a) \
    asm volatile("ldmatrix.sync.aligned.m8n8.x4.shared.b16 {%0,%1,%2,%3}, [%4];" \
        : "=r"((r)[0]), "=r"((r)[1]), "=r"((r)[2]), "=r"((r)[3]) : "r"(a))

#define MMA16816(c, a, b0, b1) \
    asm volatile("mma.sync.aligned.m16n8k16.row.col.f32.f16.f16.f32 " \
        "{%0,%1,%2,%3},{%4,%5,%6,%7},{%8,%9},{%0,%1,%2,%3};" \
        : "+f"((c)[0]), "+f"((c)[1]), "+f"((c)[2]), "+f"((c)[3]) \
        : "r"((a)[0]), "r"((a)[1]), "r"((a)[2]), "r"((a)[3]), "r"(b0), "r"(b1))

#define CPA16(dst, src) \
    asm volatile("cp.async.cg.shared.global [%0], [%1], 16;" :: "r"(dst), "l"(src))
#define CPCOMMIT() asm volatile("cp.async.commit_group;" ::: "memory")
#define CPWAIT(n)  asm volatile("cp.async.wait_group %0;" :: "n"(n) : "memory")

// ---------------- prep kernels ----------------
__global__ void __launch_bounds__(256)
prep_w(const float* __restrict__ WQ, const float* __restrict__ WK, const float* __restrict__ WV) {
    int idx = blockIdx.x * 256 + threadIdx.x;        // 3*512*512, [m][n][k]
    int m = idx >> 18;
    int r = idx & 262143;
    int n = r >> 9, k = r & 511;
    const float* W = (m == 0) ? WQ : (m == 1) ? WK : WV;
    float x = W[(size_t)k * 512 + n];
    __half h = __float2half_rn(x);
    g_wthi[idx] = h;
    g_wtlo[idx] = __float2half_rn(x - __half2float(h));
}

__global__ void __launch_bounds__(128)
prep_x(const float* __restrict__ Qs, const float* __restrict__ Ks,
       const float* __restrict__ Vs, const int* __restrict__ Qlen) {
    int gid = blockIdx.x;            // 3*32768
    int m = gid >> 15;
    int gr = gid & 32767;
    int b = gr >> 12, s = gr & 4095;
    int qa = (Qlen[b] + 127) & ~127;
    if (s >= qa) return;             // never read by GEMM
    const float* X = (m == 0) ? Qs : (m == 1) ? Ks : Vs;
    float4 v = ((const float4*)(X + ((size_t)gr << 9)))[threadIdx.x];
    union { __half h[4]; uint2 u; } H, L;
    H.h[0] = __float2half_rn(v.x); L.h[0] = __float2half_rn(v.x - __half2float(H.h[0]));
    H.h[1] = __float2half_rn(v.y); L.h[1] = __float2half_rn(v.y - __half2float(H.h[1]));
    H.h[2] = __float2half_rn(v.z); L.h[2] = __float2half_rn(v.z - __half2float(H.h[2]));
    H.h[3] = __float2half_rn(v.w); L.h[3] = __float2half_rn(v.w - __half2float(H.h[3]));
    size_t o = (((size_t)m << 15) + gr) * 512 + threadIdx.x * 4;
    *(uint2*)(g_xhi + o) = H.u;
    *(uint2*)(g_xlo + o) = L.u;
}

// ---------------- fused GEMM (HMMA) + softmax epilogue ----------------
// CTA: 64 rows x 1 head (64 cols), 256 threads, 8 warps (warp tile 16x32).
// K chunks of 32, double-buffered cp.async pipeline, 96KB smem -> 2 CTAs/SM,
// 16 warps/SM (4 per SMSP) for latency hiding.
#define TILE_B    4096
#define MAT_B     16384          // Xhi,Xlo,Whi,Wlo
#define STAGE_B   49152          // 3 matrices
#define NCHUNK    16
#define EPI_STRIDE 68            // floats per row in epilogue smem

__global__ void __launch_bounds__(256, 2)
gemm_attn(const int* __restrict__ Qlen, const int* __restrict__ Vlen, float* __restrict__ out) {
    extern __shared__ __align__(16) char dsm[];

    const int h = blockIdx.x;                  // head 0..7 (fastest -> X L2 reuse)
    const int tile = blockIdx.y;               // 0..511
    const int b = tile >> 6;
    const int s0 = (tile & 63) << 6;
    const int tid = threadIdx.x;
    const int qlen = Qlen[b];
    float* outbase = out + ((size_t)(b * 4096 + s0)) * 512 + h * 64;

    if (s0 >= qlen) {                          // whole tile masked: write zeros
        #pragma unroll
        for (int i = 0; i < 4; i++) {
            int lin = tid + i * 256;
            int r = lin >> 4, c4 = lin & 15;
            *(float4*)(outbase + (size_t)r * 512 + c4 * 4) = make_float4(0.f, 0.f, 0.f, 0.f);
        }
        return;
    }

    const uint32_t sbase = smem_u32(dsm);
    const int lane = tid & 31, wid = tid >> 5;
    const int wm = wid >> 1, wn = wid & 1;     // warp tile: rows 16*wm, cols 32*wn

    // ldmatrix logical mapping, swizzled physical address (c16 ^= (r>>1)&3)
    const int rA = wm * 16 + ((lane >> 3) & 1) * 8 + (lane & 7);
    const int cA = (lane >> 4) & 1;
    const int swA = (rA >> 1) & 3;
    const int rB = wn * 32 + ((lane >> 4) & 1) * 8 + (lane & 7);
    const int cB = (lane >> 3) & 1;
    const int swB = (rB >> 1) & 3;
    uint32_t offA[2], offB[2];
    #pragma unroll
    for (int ks = 0; ks < 2; ks++) {
        offA[ks] = (uint32_t)(rA * 64 + (((ks * 2 + cA) ^ swA) << 4));
        offB[ks] = (uint32_t)(rB * 64 + (((ks * 2 + cB) ^ swB) << 4));
    }

    float acc[3][4][4];
    #pragma unroll
    for (int m = 0; m < 3; m++)
        #pragma unroll
        for (int nt = 0; nt < 4; nt++)
            #pragma unroll
            for (int q = 0; q < 4; q++) acc[m][nt][q] = 0.f;

    const size_t xrow = (size_t)(b * 4096 + s0);

    // cp.async loader: thread -> row tid>>2, 16B-col tid&3 (12 CPA16/thread/stage)
    const int lr = tid >> 2;
    const int cc = tid & 3;
    const uint32_t lsw = (uint32_t)((lr >> 1) & 3);
    const uint32_t po = (uint32_t)(lr << 6) + (((uint32_t)cc ^ lsw) << 4);

    auto load_stage = [&](int c) {
        const int kk0 = (c & 15) << 5;
        const uint32_t sb = sbase + (c & 1) * STAGE_B;
        #pragma unroll
        for (int m = 0; m < 3; m++) {
            const size_t xg = ((size_t)(m << 15) + xrow + lr) * 512 + kk0 + cc * 8;
            const size_t wg = ((size_t)(m * 512 + h * 64 + lr)) * 512 + kk0 + cc * 8;
            const uint32_t mb = sb + m * MAT_B;
            CPA16(mb + po,              g_xhi  + xg);
            CPA16(mb + TILE_B + po,     g_xlo  + xg);
            CPA16(mb + 2 * TILE_B + po, g_wthi + wg);
            CPA16(mb + 3 * TILE_B + po, g_wtlo + wg);
        }
        CPCOMMIT();
    };

    auto compute = [&](int c) {
        const uint32_t sb = sbase + (c & 1) * STAGE_B;
        #pragma unroll
        for (int ks = 0; ks < 2; ks++) {
            #pragma unroll
            for (int m = 0; m < 3; m++) {
                const uint32_t mb = sb + m * MAT_B;
                uint32_t aH[4], aL[4], bH[2][4], bL[2][4];
                LDSM4(aH, mb + offA[ks]);
                LDSM4(aL, mb + TILE_B + offA[ks]);
                LDSM4(bH[0], mb + 2 * TILE_B + offB[ks]);
                LDSM4(bH[1], mb + 2 * TILE_B + offB[ks] + 1024);
                LDSM4(bL[0], mb + 3 * TILE_B + offB[ks]);
                LDSM4(bL[1], mb + 3 * TILE_B + offB[ks] + 1024);
                #pragma unroll
                for (int nt = 0; nt < 4; nt++) {
                    const int nb = nt >> 1, p = (nt & 1) * 2;
                    MMA16816(acc[m][nt], aH, bH[nb][p], bH[nb][p + 1]);
                    MMA16816(acc[m][nt], aH, bL[nb][p], bL[nb][p + 1]);
                    MMA16816(acc[m][nt], aL, bH[nb][p], bH[nb][p + 1]);
                }
            }
        }
    };

    load_stage(0);
    load_stage(1);
    for (int c = 0; c < NCHUNK; c++) {
        if (c < NCHUNK - 1) { CPWAIT(1); } else { CPWAIT(0); }
        __syncthreads();
        compute(c);
        __syncthreads();
        if (c + 2 < NCHUNK) load_stage(c + 2);
    }

    // ---- epilogue: dump accs to smem (reuse tile buffers), per-row softmax ----
    {
        float* sepi = (float*)dsm;
        const int g = lane >> 2, t = lane & 3;
        #pragma unroll
        for (int m = 0; m < 3; m++)
            #pragma unroll
            for (int nt = 0; nt < 4; nt++) {
                float* p = sepi + (size_t)((m * 64 + wm * 16 + g) * EPI_STRIDE
                                           + wn * 32 + nt * 8 + 2 * t);
                p[0] = acc[m][nt][0];
                p[1] = acc[m][nt][1];
                p[8 * EPI_STRIDE]     = acc[m][nt][2];
                p[8 * EPI_STRIDE + 1] = acc[m][nt][3];
            }
        __syncthreads();

        const int row = tid >> 2, qd = tid & 3;    // thread = (row, 16-col quarter)
        const int vlen = Vlen[b];
        float q[16], k[16], v[16];
        #pragma unroll
        for (int j = 0; j < 4; j++) {
            *(float4*)&q[j * 4] = *(float4*)&sepi[(0 * 64 + row) * EPI_STRIDE + qd * 16 + j * 4];
            *(float4*)&k[j * 4] = *(float4*)&sepi[(1 * 64 + row) * EPI_STRIDE + qd * 16 + j * 4];
            *(float4*)&v[j * 4] = *(float4*)&sepi[(2 * 64 + row) * EPI_STRIDE + qd * 16 + j * 4];
        }
        float l[16];
        #pragma unroll
        for (int j = 0; j < 16; j++) {
            l[j] = q[j] * k[j] * 0.125f;
            if (qd * 16 + j >= vlen) l[j] -= 1e12f;
        }
        float mx = l[0];
        #pragma unroll
        for (int j = 1; j < 16; j++) mx = fmaxf(mx, l[j]);
        mx = fmaxf(mx, __shfl_xor_sync(0xffffffffu, mx, 1));
        mx = fmaxf(mx, __shfl_xor_sync(0xffffffffu, mx, 2));
        float sum = 0.f;
        #pragma unroll
        for (int j = 0; j < 16; j++) { l[j] = expf(l[j] - mx); sum += l[j]; }
        sum += __shfl_xor_sync(0xffffffffu, sum, 1);
        sum += __shfl_xor_sync(0xffffffffu, sum, 2);
        float sc = 1.0f / sum;
        if (s0 + row >= qlen) sc = 0.f;        // qmask
        float* op = outbase + (size_t)row * 512 + qd * 16;
        #pragma unroll
        for (int j = 0; j < 4; j++) {
            float4 o4 = make_float4(l[j * 4 + 0] * v[j * 4 + 0] * sc,
                                    l[j * 4 + 1] * v[j * 4 + 1] * sc,
                                    l[j * 4 + 2] * v[j * 4 + 2] * sc,
                                    l[j * 4 + 3] * v[j * 4 + 3] * sc);
            *(float4*)(op + j * 4) = o4;
        }
    }
}

// ---------------- launch ----------------
extern "C" void kernel_launch(void* const* d_in, const int* in_sizes, int n_in,
                              void* d_out, int out_size) {
    (void)in_sizes; (void)n_in; (void)out_size;
    const float* Qs = (const float*)d_in[0];
    const float* Ks = (const float*)d_in[1];
    const float* Vs = (const float*)d_in[2];
    const int*   Ql = (const int*)d_in[3];
    const int*   Vl = (const int*)d_in[4];
    const float* WQ = (const float*)d_in[5];
    const float* WK = (const float*)d_in[6];
    const float* WV = (const float*)d_in[7];

    static int smem_set = 0;
    if (!smem_set) {
        cudaFuncSetAttribute(gemm_attn, cudaFuncAttributeMaxDynamicSharedMemorySize,
                             2 * STAGE_B);
        smem_set = 1;
    }

    prep_w<<<3072, 256>>>(WQ, WK, WV);
    prep_x<<<98304, 128>>>(Qs, Ks, Vs, Ql);
    gemm_attn<<<dim3(8, 512), 256, 2 * STAGE_B>>>(Ql, Vl, (float*)d_out);
}

// round 7
// speedup vs baseline: 3.2498x; 1.1184x over previous
#include <cuda_runtime.h>
#include <cuda_fp16.h>
#include <cstdint>

// ---------------- scratch (static __device__, no allocs) ----------------
#define XN (3u*32768u*512u)
#define WN (3u*512u*512u)
__device__ __half g_xhi[XN];
__device__ __half g_xlo[XN];
__device__ __half g_wthi[WN];   // [m][n][k] fp16, K-major (W transposed)
__device__ __half g_wtlo[WN];

__device__ __forceinline__ uint32_t smem_u32(const void* p) {
    uint32_t a;
    asm("{ .reg .u64 t; cvta.to.shared.u64 t, %1; cvt.u32.u64 %0, t; }" : "=r"(a) : "l"(p));
    return a;
}

#define LDSM4(r, a) \
    asm volatile("ldmatrix.sync.aligned.m8n8.x4.shared.b16 {%0,%1,%2,%3}, [%4];" \
        : "=r"((r)[0]), "=r"((r)[1]), "=r"((r)[2]), "=r"((r)[3]) : "r"(a))

#define MMA16816(c, a, b0, b1) \
    asm volatile("mma.sync.aligned.m16n8k16.row.col.f32.f16.f16.f32 " \
        "{%0,%1,%2,%3},{%4,%5,%6,%7},{%8,%9},{%0,%1,%2,%3};" \
        : "+f"((c)[0]), "+f"((c)[1]), "+f"((c)[2]), "+f"((c)[3]) \
        : "r"((a)[0]), "r"((a)[1]), "r"((a)[2]), "r"((a)[3]), "r"(b0), "r"(b1))

#define CPA16(dst, src) \
    asm volatile("cp.async.cg.shared.global [%0], [%1], 16;" :: "r"(dst), "l"(src))
#define CPCOMMIT() asm volatile("cp.async.commit_group;" ::: "memory")
#define CPWAIT(n)  asm volatile("cp.async.wait_group %0;" :: "n"(n) : "memory")

// ---------------- prep kernels ----------------
__global__ void __launch_bounds__(256)
prep_w(const float* __restrict__ WQ, const float* __restrict__ WK, const float* __restrict__ WV) {
    int idx = blockIdx.x * 256 + threadIdx.x;        // 3*512*512, [m][n][k]
    int m = idx >> 18;
    int r = idx & 262143;
    int n = r >> 9, k = r & 511;
    const float* W = (m == 0) ? WQ : (m == 1) ? WK : WV;
    float x = W[(size_t)k * 512 + n];
    __half h = __float2half_rn(x);
    g_wthi[idx] = h;
    if (m < 2) g_wtlo[idx] = __float2half_rn(x - __half2float(h));
}

__global__ void __launch_bounds__(128)
prep_x(const float* __restrict__ Qs, const float* __restrict__ Ks,
       const float* __restrict__ Vs, const int* __restrict__ Qlen) {
    int gid = blockIdx.x;            // 3*32768
    int m = gid >> 15;
    int gr = gid & 32767;
    int b = gr >> 12, s = gr & 4095;
    int qa = (Qlen[b] + 63) & ~63;
    if (s >= qa) return;             // never read by GEMM
    const float* X = (m == 0) ? Qs : (m == 1) ? Ks : Vs;
    float4 v = ((const float4*)(X + ((size_t)gr << 9)))[threadIdx.x];
    union { __half h[4]; uint2 u; } H, L;
    H.h[0] = __float2half_rn(v.x); L.h[0] = __float2half_rn(v.x - __half2float(H.h[0]));
    H.h[1] = __float2half_rn(v.y); L.h[1] = __float2half_rn(v.y - __half2float(H.h[1]));
    H.h[2] = __float2half_rn(v.z); L.h[2] = __float2half_rn(v.z - __half2float(H.h[2]));
    H.h[3] = __float2half_rn(v.w); L.h[3] = __float2half_rn(v.w - __half2float(H.h[3]));
    size_t o = (((size_t)m << 15) + gr) * 512 + threadIdx.x * 4;
    *(uint2*)(g_xhi + o) = H.u;
    if (m < 2) *(uint2*)(g_xlo + o) = L.u;
}

// ---------------- fused GEMM (HMMA) + softmax epilogue ----------------
// CTA: 64 rows x 2 heads (N=128), 512 threads, 16 warps (warp tile 16x32).
// Q/K: 3-product fp16 split; V: single fp16 product (enters output linearly).
// K chunks of 32, 3-stage cp.async pipeline (one barrier per chunk).
// Swizzled layout: row stride 64B, 16B-col c ^= (r>>1)&3.
// Stage tiles: XQhi XQlo XKhi XKlo XVhi (5 x 4KB), WQhi WQlo WKhi WKlo WVhi (5 x 8KB)
#define XQHI 0
#define XQLO 4096
#define XKHI 8192
#define XKLO 12288
#define XVHI 16384
#define WQHI 20480
#define WQLO 28672
#define WKHI 36864
#define WKLO 45056
#define WVHI 53248
#define STAGE_B 61440
#define NCHUNK  16
#define ESTR    132              // floats per row in epilogue smem

__global__ void __launch_bounds__(512, 1)
gemm_attn(const int* __restrict__ Qlen, const int* __restrict__ Vlen, float* __restrict__ out) {
    extern __shared__ __align__(16) char dsm[];

    const int hp = blockIdx.x;                 // head pair 0..3
    const int tile = blockIdx.y;               // 0..511
    const int b = tile >> 6;
    const int s0 = (tile & 63) << 6;
    const int tid = threadIdx.x;
    const int qlen = Qlen[b];
    float* outbase = out + ((size_t)(b * 4096 + s0)) * 512 + hp * 128;

    if (s0 >= qlen) {                          // whole tile masked: write zeros
        #pragma unroll
        for (int i = 0; i < 4; i++) {
            int lin = tid + i * 512;
            int r = lin >> 5, c4 = lin & 31;
            *(float4*)(outbase + (size_t)r * 512 + c4 * 4) = make_float4(0.f, 0.f, 0.f, 0.f);
        }
        return;
    }

    const uint32_t sbase = smem_u32(dsm);
    const int lane = tid & 31, wid = tid >> 5;
    const int wm = wid >> 2, wn = wid & 3;     // warp tile: rows 16*wm, cols 32*wn

    // ldmatrix logical mapping, swizzled physical address (c16 ^= (r>>1)&3)
    const int rA = wm * 16 + ((lane >> 3) & 1) * 8 + (lane & 7);
    const int cA = (lane >> 4) & 1;
    const int swA = (rA >> 1) & 3;
    const int rB = wn * 32 + ((lane >> 4) & 1) * 8 + (lane & 7);
    const int cB = (lane >> 3) & 1;
    const int swB = (rB >> 1) & 3;
    uint32_t offA[2], offB[2];
    #pragma unroll
    for (int ks = 0; ks < 2; ks++) {
        offA[ks] = (uint32_t)(rA * 64 + (((ks * 2 + cA) ^ swA) << 4));
        offB[ks] = (uint32_t)(rB * 64 + (((ks * 2 + cB) ^ swB) << 4));
    }

    float acc[3][4][4];
    #pragma unroll
    for (int m = 0; m < 3; m++)
        #pragma unroll
        for (int nt = 0; nt < 4; nt++)
            #pragma unroll
            for (int q = 0; q < 4; q++) acc[m][nt][q] = 0.f;

    const size_t xrow = (size_t)(b * 4096 + s0);

    // loaders: X (64 rows) -> threads < 256; W (128 rows) -> all threads
    const int xlr = tid >> 2, xcc = tid & 3;
    const uint32_t xpo = (uint32_t)(xlr << 6) + ((((uint32_t)xcc) ^ ((xlr >> 1) & 3)) << 4);
    const int wlr = tid >> 2, wcc = tid & 3;   // wlr 0..127
    const uint32_t wpo = (uint32_t)(wlr << 6) + ((((uint32_t)wcc) ^ ((wlr >> 1) & 3)) << 4);

    auto load_stage = [&](int c) {
        const int kk0 = (c & 15) << 5;
        const uint32_t sb = sbase + (c % 3) * STAGE_B;
        {   // W tiles: all 512 threads
            const size_t wgQ = ((size_t)(0 * 512 + hp * 128 + wlr)) * 512 + kk0 + wcc * 8;
            const size_t wgK = ((size_t)(1 * 512 + hp * 128 + wlr)) * 512 + kk0 + wcc * 8;
            const size_t wgV = ((size_t)(2 * 512 + hp * 128 + wlr)) * 512 + kk0 + wcc * 8;
            CPA16(sb + WQHI + wpo, g_wthi + wgQ);
            CPA16(sb + WQLO + wpo, g_wtlo + wgQ);
            CPA16(sb + WKHI + wpo, g_wthi + wgK);
            CPA16(sb + WKLO + wpo, g_wtlo + wgK);
            CPA16(sb + WVHI + wpo, g_wthi + wgV);
        }
        if (tid < 256) {  // X tiles
            const size_t xgQ = ((size_t)(0 << 15) + xrow + xlr) * 512 + kk0 + xcc * 8;
            const size_t xgK = ((size_t)(1 << 15) + xrow + xlr) * 512 + kk0 + xcc * 8;
            const size_t xgV = ((size_t)(2 << 15) + xrow + xlr) * 512 + kk0 + xcc * 8;
            CPA16(sb + XQHI + xpo, g_xhi + xgQ);
            CPA16(sb + XQLO + xpo, g_xlo + xgQ);
            CPA16(sb + XKHI + xpo, g_xhi + xgK);
            CPA16(sb + XKLO + xpo, g_xlo + xgK);
            CPA16(sb + XVHI + xpo, g_xhi + xgV);
        }
        CPCOMMIT();
    };

    auto compute = [&](int c) {
        const uint32_t sb = sbase + (c % 3) * STAGE_B;
        #pragma unroll
        for (int ks = 0; ks < 2; ks++) {
            uint32_t aH[4], aL[4], bH[2][4], bL[2][4];
            // ---- Q: 3 products ----
            LDSM4(aH, sb + XQHI + offA[ks]);
            LDSM4(aL, sb + XQLO + offA[ks]);
            LDSM4(bH[0], sb + WQHI + offB[ks]);
            LDSM4(bH[1], sb + WQHI + offB[ks] + 1024);
            LDSM4(bL[0], sb + WQLO + offB[ks]);
            LDSM4(bL[1], sb + WQLO + offB[ks] + 1024);
            #pragma unroll
            for (int nt = 0; nt < 4; nt++) {
                const int nb = nt >> 1, p = (nt & 1) * 2;
                MMA16816(acc[0][nt], aH, bH[nb][p], bH[nb][p + 1]);
                MMA16816(acc[0][nt], aH, bL[nb][p], bL[nb][p + 1]);
                MMA16816(acc[0][nt], aL, bH[nb][p], bH[nb][p + 1]);
            }
            // ---- K: 3 products ----
            LDSM4(aH, sb + XKHI + offA[ks]);
            LDSM4(aL, sb + XKLO + offA[ks]);
            LDSM4(bH[0], sb + WKHI + offB[ks]);
            LDSM4(bH[1], sb + WKHI + offB[ks] + 1024);
            LDSM4(bL[0], sb + WKLO + offB[ks]);
            LDSM4(bL[1], sb + WKLO + offB[ks] + 1024);
            #pragma unroll
            for (int nt = 0; nt < 4; nt++) {
                const int nb = nt >> 1, p = (nt & 1) * 2;
                MMA16816(acc[1][nt], aH, bH[nb][p], bH[nb][p + 1]);
                MMA16816(acc[1][nt], aH, bL[nb][p], bL[nb][p + 1]);
                MMA16816(acc[1][nt], aL, bH[nb][p], bH[nb][p + 1]);
            }
            // ---- V: single product ----
            LDSM4(aH, sb + XVHI + offA[ks]);
            LDSM4(bH[0], sb + WVHI + offB[ks]);
            LDSM4(bH[1], sb + WVHI + offB[ks] + 1024);
            #pragma unroll
            for (int nt = 0; nt < 4; nt++) {
                const int nb = nt >> 1, p = (nt & 1) * 2;
                MMA16816(acc[2][nt], aH, bH[nb][p], bH[nb][p + 1]);
            }
        }
    };

    load_stage(0);
    load_stage(1);
    for (int c = 0; c < NCHUNK; c++) {
        if (c < NCHUNK - 1) { CPWAIT(1); } else { CPWAIT(0); }
        __syncthreads();
        compute(c);
        if (c + 2 < NCHUNK) load_stage(c + 2);
    }
    __syncthreads();

    // ---- epilogue: dump accs to smem (reuse tile buffers), per-(row,head) softmax ----
    {
        float* sepi = (float*)dsm;
        const int g = lane >> 2, t = lane & 3;
        #pragma unroll
        for (int m = 0; m < 3; m++)
            #pragma unroll
            for (int nt = 0; nt < 4; nt++) {
                float* p = sepi + (size_t)((m * 64 + wm * 16 + g) * ESTR
                                           + wn * 32 + nt * 8 + 2 * t);
                p[0] = acc[m][nt][0];
                p[1] = acc[m][nt][1];
                p[8 * ESTR]     = acc[m][nt][2];
                p[8 * ESTR + 1] = acc[m][nt][3];
            }
        __syncthreads();

        const int row = tid >> 3;               // 0..63
        const int hh  = (tid >> 2) & 1;         // head within pair
        const int qd  = tid & 3;                // 16-col quarter within head
        const int vlen = Vlen[b];
        const int cb = hh * 64 + qd * 16;
        float q[16], k[16], v[16];
        #pragma unroll
        for (int j = 0; j < 4; j++) {
            *(float4*)&q[j * 4] = *(float4*)&sepi[(0 * 64 + row) * ESTR + cb + j * 4];
            *(float4*)&k[j * 4] = *(float4*)&sepi[(1 * 64 + row) * ESTR + cb + j * 4];
            *(float4*)&v[j * 4] = *(float4*)&sepi[(2 * 64 + row) * ESTR + cb + j * 4];
        }
        float l[16];
        #pragma unroll
        for (int j = 0; j < 16; j++) {
            l[j] = q[j] * k[j] * 0.125f;
            if (qd * 16 + j >= vlen) l[j] -= 1e12f;
        }
        float mx = l[0];
        #pragma unroll
        for (int j = 1; j < 16; j++) mx = fmaxf(mx, l[j]);
        mx = fmaxf(mx, __shfl_xor_sync(0xffffffffu, mx, 1));
        mx = fmaxf(mx, __shfl_xor_sync(0xffffffffu, mx, 2));
        float sum = 0.f;
        #pragma unroll
        for (int j = 0; j < 16; j++) { l[j] = expf(l[j] - mx); sum += l[j]; }
        sum += __shfl_xor_sync(0xffffffffu, sum, 1);
        sum += __shfl_xor_sync(0xffffffffu, sum, 2);
        float sc = 1.0f / sum;
        if (s0 + row >= qlen) sc = 0.f;        // qmask
        float* op = outbase + (size_t)row * 512 + cb;
        #pragma unroll
        for (int j = 0; j < 4; j++) {
            float4 o4 = make_float4(l[j * 4 + 0] * v[j * 4 + 0] * sc,
                                    l[j * 4 + 1] * v[j * 4 + 1] * sc,
                                    l[j * 4 + 2] * v[j * 4 + 2] * sc,
                                    l[j * 4 + 3] * v[j * 4 + 3] * sc);
            *(float4*)(op + j * 4) = o4;
        }
    }
}

// ---------------- launch ----------------
extern "C" void kernel_launch(void* const* d_in, const int* in_sizes, int n_in,
                              void* d_out, int out_size) {
    (void)in_sizes; (void)n_in; (void)out_size;
    const float* Qs = (const float*)d_in[0];
    const float* Ks = (const float*)d_in[1];
    const float* Vs = (const float*)d_in[2];
    const int*   Ql = (const int*)d_in[3];
    const int*   Vl = (const int*)d_in[4];
    const float* WQ = (const float*)d_in[5];
    const float* WK = (const float*)d_in[6];
    const float* WV = (const float*)d_in[7];

    static int smem_set = 0;
    if (!smem_set) {
        cudaFuncSetAttribute(gemm_attn, cudaFuncAttributeMaxDynamicSharedMemorySize,
                             3 * STAGE_B);
        smem_set = 1;
    }

    prep_w<<<3072, 256>>>(WQ, WK, WV);
    prep_x<<<98304, 128>>>(Qs, Ks, Vs, Ql);
    gemm_attn<<<dim3(4, 512), 512, 3 * STAGE_B>>>(Ql, Vl, (float*)d_out);
}

// round 9
// speedup vs baseline: 3.3185x; 1.0211x over previous
#include <cuda_runtime.h>
#include <cuda_fp16.h>
#include <cstdint>

// ---------------- scratch (static __device__, no allocs) ----------------
#define XN (3u*32768u*512u)
#define WN (3u*512u*512u)
__device__ __half g_xhi[XN];
__device__ __half g_xlo[XN];
__device__ __half g_wthi[WN];   // [m][n][k] fp16, K-major (W transposed)
__device__ __half g_wtlo[WN];

__device__ __forceinline__ uint32_t smem_u32(const void* p) {
    uint32_t a;
    asm("{ .reg .u64 t; cvta.to.shared.u64 t, %1; cvt.u32.u64 %0, t; }" : "=r"(a) : "l"(p));
    return a;
}

#define LDSM4(r, a) \
    asm volatile("ldmatrix.sync.aligned.m8n8.x4.shared.b16 {%0,%1,%2,%3}, [%4];" \
        : "=r"((r)[0]), "=r"((r)[1]), "=r"((r)[2]), "=r"((r)[3]) : "r"(a))

#define MMA16816(c, a, b0, b1) \
    asm volatile("mma.sync.aligned.m16n8k16.row.col.f32.f16.f16.f32 " \
        "{%0,%1,%2,%3},{%4,%5,%6,%7},{%8,%9},{%0,%1,%2,%3};" \
        : "+f"((c)[0]), "+f"((c)[1]), "+f"((c)[2]), "+f"((c)[3]) \
        : "r"((a)[0]), "r"((a)[1]), "r"((a)[2]), "r"((a)[3]), "r"(b0), "r"(b1))

#define CPA16(dst, src) \
    asm volatile("cp.async.cg.shared.global [%0], [%1], 16;" :: "r"(dst), "l"(src))
#define CPCOMMIT() asm volatile("cp.async.commit_group;" ::: "memory")
#define CPWAIT(n)  asm volatile("cp.async.wait_group %0;" :: "n"(n) : "memory")

// ---------------- fused prep kernel ----------------
// blocks [0, 98304): X split (one row each, 128 threads)
// blocks [98304, 104448): W transpose+split (128 elems each)
#define XBLOCKS 98304
__global__ void __launch_bounds__(128)
prep_all(const float* __restrict__ Qs, const float* __restrict__ Ks,
         const float* __restrict__ Vs, const int* __restrict__ Qlen,
         const float* __restrict__ WQ, const float* __restrict__ WK,
         const float* __restrict__ WV) {
    if (blockIdx.x < XBLOCKS) {
        int gid = blockIdx.x;            // 3*32768
        int m = gid >> 15;
        int gr = gid & 32767;
        int b = gr >> 12, s = gr & 4095;
        int qa = (Qlen[b] + 63) & ~63;
        if (s >= qa) return;             // never read by GEMM
        const float* X = (m == 0) ? Qs : (m == 1) ? Ks : Vs;
        float4 v = ((const float4*)(X + ((size_t)gr << 9)))[threadIdx.x];
        union { __half h[4]; uint2 u; } H, L;
        H.h[0] = __float2half_rn(v.x); L.h[0] = __float2half_rn(v.x - __half2float(H.h[0]));
        H.h[1] = __float2half_rn(v.y); L.h[1] = __float2half_rn(v.y - __half2float(H.h[1]));
        H.h[2] = __float2half_rn(v.z); L.h[2] = __float2half_rn(v.z - __half2float(H.h[2]));
        H.h[3] = __float2half_rn(v.w); L.h[3] = __float2half_rn(v.w - __half2float(H.h[3]));
        size_t o = (((size_t)m << 15) + gr) * 512 + threadIdx.x * 4;
        *(uint2*)(g_xhi + o) = H.u;
        if (m < 2) *(uint2*)(g_xlo + o) = L.u;
    } else {
        int idx = (blockIdx.x - XBLOCKS) * 128 + threadIdx.x;   // 3*512*512, [m][n][k]
        int m = idx >> 18;
        int r = idx & 262143;
        int n = r >> 9, k = r & 511;
        const float* W = (m == 0) ? WQ : (m == 1) ? WK : WV;
        float x = W[(size_t)k * 512 + n];
        __half h = __float2half_rn(x);
        g_wthi[idx] = h;
        if (m < 2) g_wtlo[idx] = __float2half_rn(x - __half2float(h));
    }
}

// ---------------- fused GEMM (HMMA) + softmax epilogue ----------------
// CTA: 64 rows x 2 heads (N=128), 512 threads, 16 warps (warp tile 16x32).
// Q/K: 3-product fp16 split; V: single fp16 product.
// V_len column culling: only head-cols < vlen computed (vlen==0 -> V full, no Q/K).
// K chunks of 32, 3-stage cp.async pipeline. Swizzle: 64B rows, c16 ^= (r>>1)&3.
#define XQHI 0
#define XQLO 4096
#define XKHI 8192
#define XKLO 12288
#define XVHI 16384
#define WQHI 20480
#define WQLO 28672
#define WKHI 36864
#define WKLO 45056
#define WVHI 53248
#define STAGE_B 61440
#define NCHUNK  16
#define ESTR    132              // floats per row in epilogue smem

__global__ void __launch_bounds__(512, 1)
gemm_attn(const int* __restrict__ Qlen, const int* __restrict__ Vlen, float* __restrict__ out) {
    extern __shared__ __align__(16) char dsm[];

    const int hp = blockIdx.x;                 // head pair 0..3
    const int tile = blockIdx.y;               // 0..511
    const int b = tile >> 6;
    const int s0 = (tile & 63) << 6;
    const int tid = threadIdx.x;
    const int qlen = Qlen[b];
    float* outbase = out + ((size_t)(b * 4096 + s0)) * 512 + hp * 128;

    if (s0 >= qlen) {                          // whole tile masked: write zeros
        #pragma unroll
        for (int i = 0; i < 4; i++) {
            int lin = tid + i * 512;
            int r = lin >> 5, c4 = lin & 31;
            *(float4*)(outbase + (size_t)r * 512 + c4 * 4) = make_float4(0.f, 0.f, 0.f, 0.f);
        }
        return;
    }

    const int vlen = Vlen[b];
    const int nQK = vlen;                      // head-cols of Q/K needed
    const int nV  = (vlen == 0) ? 64 : vlen;   // head-cols of V needed
    const int nWQK = (nQK + 15) & ~15;         // W rows to load (LDSM coverage)
    const int nWV  = (nV + 15) & ~15;

    const uint32_t sbase = smem_u32(dsm);
    const int lane = tid & 31, wid = tid >> 5;
    const int wm = wid >> 2, wn = wid & 3;     // warp tile: rows 16*wm, cols 32*wn
    const int cbw = (wn & 1) * 32;             // head-local col base of this warp

    // ldmatrix logical mapping, swizzled physical address (c16 ^= (r>>1)&3)
    const int rA = wm * 16 + ((lane >> 3) & 1) * 8 + (lane & 7);
    const int cA = (lane >> 4) & 1;
    const int swA = (rA >> 1) & 3;
    const int rB = wn * 32 + ((lane >> 4) & 1) * 8 + (lane & 7);
    const int cB = (lane >> 3) & 1;
    const int swB = (rB >> 1) & 3;
    uint32_t offA[2], offB[2];
    #pragma unroll
    for (int ks = 0; ks < 2; ks++) {
        offA[ks] = (uint32_t)(rA * 64 + (((ks * 2 + cA) ^ swA) << 4));
        offB[ks] = (uint32_t)(rB * 64 + (((ks * 2 + cB) ^ swB) << 4));
    }

    float acc[3][4][4];
    #pragma unroll
    for (int m = 0; m < 3; m++)
        #pragma unroll
        for (int nt = 0; nt < 4; nt++)
            #pragma unroll
            for (int q = 0; q < 4; q++) acc[m][nt][q] = 0.f;

    const size_t xrow = (size_t)(b * 4096 + s0);

    // loaders: X (64 rows) -> threads < 256; W (128 rows) -> all threads
    const int xlr = tid >> 2, xcc = tid & 3;
    const uint32_t xpo = (uint32_t)(xlr << 6) + ((((uint32_t)xcc) ^ ((xlr >> 1) & 3)) << 4);
    const int wlr = tid >> 2, wcc = tid & 3;   // wlr 0..127
    const int w63 = wlr & 63;                  // head-local W row
    const uint32_t wpo = (uint32_t)(wlr << 6) + ((((uint32_t)wcc) ^ ((wlr >> 1) & 3)) << 4);

    auto load_stage = [&](int c) {
        const int kk0 = (c & 15) << 5;
        const uint32_t sb = sbase + (c % 3) * STAGE_B;
        {   // W tiles, predicated by needed rows
            const size_t wgQ = ((size_t)(0 * 512 + hp * 128 + wlr)) * 512 + kk0 + wcc * 8;
            const size_t wgK = ((size_t)(1 * 512 + hp * 128 + wlr)) * 512 + kk0 + wcc * 8;
            const size_t wgV = ((size_t)(2 * 512 + hp * 128 + wlr)) * 512 + kk0 + wcc * 8;
            if (w63 < nWQK) {
                CPA16(sb + WQHI + wpo, g_wthi + wgQ);
                CPA16(sb + WQLO + wpo, g_wtlo + wgQ);
                CPA16(sb + WKHI + wpo, g_wthi + wgK);
                CPA16(sb + WKLO + wpo, g_wtlo + wgK);
            }
            if (w63 < nWV) CPA16(sb + WVHI + wpo, g_wthi + wgV);
        }
        if (tid < 256) {  // X tiles
            const size_t xgQ = ((size_t)(0 << 15) + xrow + xlr) * 512 + kk0 + xcc * 8;
            const size_t xgK = ((size_t)(1 << 15) + xrow + xlr) * 512 + kk0 + xcc * 8;
            const size_t xgV = ((size_t)(2 << 15) + xrow + xlr) * 512 + kk0 + xcc * 8;
            if (nQK > 0) {
                CPA16(sb + XQHI + xpo, g_xhi + xgQ);
                CPA16(sb + XQLO + xpo, g_xlo + xgQ);
                CPA16(sb + XKHI + xpo, g_xhi + xgK);
                CPA16(sb + XKLO + xpo, g_xlo + xgK);
            }
            CPA16(sb + XVHI + xpo, g_xhi + xgV);
        }
        CPCOMMIT();
    };

    auto compute = [&](int c) {
        const uint32_t sb = sbase + (c % 3) * STAGE_B;
        #pragma unroll
        for (int ks = 0; ks < 2; ks++) {
            uint32_t aH[4], aL[4], bH[2][4], bL[2][4];
            // ---- Q: 3 products ----
            if (cbw < nQK) {
                LDSM4(aH, sb + XQHI + offA[ks]);
                LDSM4(aL, sb + XQLO + offA[ks]);
                LDSM4(bH[0], sb + WQHI + offB[ks]);
                LDSM4(bL[0], sb + WQLO + offB[ks]);
                if (cbw + 16 < nQK) {
                    LDSM4(bH[1], sb + WQHI + offB[ks] + 1024);
                    LDSM4(bL[1], sb + WQLO + offB[ks] + 1024);
                }
                #pragma unroll
                for (int nt = 0; nt < 4; nt++) {
                    if (cbw + nt * 8 < nQK) {
                        const int nb = nt >> 1, p = (nt & 1) * 2;
                        MMA16816(acc[0][nt], aH, bH[nb][p], bH[nb][p + 1]);
                        MMA16816(acc[0][nt], aH, bL[nb][p], bL[nb][p + 1]);
                        MMA16816(acc[0][nt], aL, bH[nb][p], bH[nb][p + 1]);
                    }
                }
                // ---- K: 3 products ----
                LDSM4(aH, sb + XKHI + offA[ks]);
                LDSM4(aL, sb + XKLO + offA[ks]);
                LDSM4(bH[0], sb + WKHI + offB[ks]);
                LDSM4(bL[0], sb + WKLO + offB[ks]);
                if (cbw + 16 < nQK) {
                    LDSM4(bH[1], sb + WKHI + offB[ks] + 1024);
                    LDSM4(bL[1], sb + WKLO + offB[ks] + 1024);
                }
                #pragma unroll
                for (int nt = 0; nt < 4; nt++) {
                    if (cbw + nt * 8 < nQK) {
                        const int nb = nt >> 1, p = (nt & 1) * 2;
                        MMA16816(acc[1][nt], aH, bH[nb][p], bH[nb][p + 1]);
                        MMA16816(acc[1][nt], aH, bL[nb][p], bL[nb][p + 1]);
                        MMA16816(acc[1][nt], aL, bH[nb][p], bH[nb][p + 1]);
                    }
                }
            }
            // ---- V: single product ----
            if (cbw < nV) {
                LDSM4(aH, sb + XVHI + offA[ks]);
                LDSM4(bH[0], sb + WVHI + offB[ks]);
                if (cbw + 16 < nV) LDSM4(bH[1], sb + WVHI + offB[ks] + 1024);
                #pragma unroll
                for (int nt = 0; nt < 4; nt++) {
                    if (cbw + nt * 8 < nV) {
                        const int nb = nt >> 1, p = (nt & 1) * 2;
                        MMA16816(acc[2][nt], aH, bH[nb][p], bH[nb][p + 1]);
                    }
                }
            }
        }
    };

    load_stage(0);
    load_stage(1);
    for (int c = 0; c < NCHUNK; c++) {
        if (c < NCHUNK - 1) { CPWAIT(1); } else { CPWAIT(0); }
        __syncthreads();
        compute(c);
        if (c + 2 < NCHUNK) load_stage(c + 2);
    }
    __syncthreads();

    // ---- epilogue: dump accs to smem (reuse tile buffers), per-(row,head) softmax ----
    {
        float* sepi = (float*)dsm;
        const int g = lane >> 2, t = lane & 3;
        #pragma unroll
        for (int m = 0; m < 3; m++)
            #pragma unroll
            for (int nt = 0; nt < 4; nt++) {
                float* p = sepi + (size_t)((m * 64 + wm * 16 + g) * ESTR
                                           + wn * 32 + nt * 8 + 2 * t);
                p[0] = acc[m][nt][0];
                p[1] = acc[m][nt][1];
                p[8 * ESTR]     = acc[m][nt][2];
                p[8 * ESTR + 1] = acc[m][nt][3];
            }
        __syncthreads();

        const int row = tid >> 3;               // 0..63
        const int hh  = (tid >> 2) & 1;         // head within pair
        const int qd  = tid & 3;                // 16-col quarter within head
        const int cb = hh * 64 + qd * 16;
        float q[16], k[16], v[16];
        #pragma unroll
        for (int j = 0; j < 4; j++) {
            *(float4*)&q[j * 4] = *(float4*)&sepi[(0 * 64 + row) * ESTR + cb + j * 4];
            *(float4*)&k[j * 4] = *(float4*)&sepi[(1 * 64 + row) * ESTR + cb + j * 4];
            *(float4*)&v[j * 4] = *(float4*)&sepi[(2 * 64 + row) * ESTR + cb + j * 4];
        }
        float l[16];
        #pragma unroll
        for (int j = 0; j < 16; j++) {
            l[j] = q[j] * k[j] * 0.125f;
            if (qd * 16 + j >= vlen) l[j] -= 1e12f;
        }
        float mx = l[0];
        #pragma unroll
        for (int j = 1; j < 16; j++) mx = fmaxf(mx, l[j]);
        mx = fmaxf(mx, __shfl_xor_sync(0xffffffffu, mx, 1));
        mx = fmaxf(mx, __shfl_xor_sync(0xffffffffu, mx, 2));
        float sum = 0.f;
        #pragma unroll
        for (int j = 0; j < 16; j++) { l[j] = expf(l[j] - mx); sum += l[j]; }
        sum += __shfl_xor_sync(0xffffffffu, sum, 1);
        sum += __shfl_xor_sync(0xffffffffu, sum, 2);
        float sc = 1.0f / sum;
        if (s0 + row >= qlen) sc = 0.f;        // qmask
        float* op = outbase + (size_t)row * 512 + cb;
        #pragma unroll
        for (int j = 0; j < 4; j++) {
            float4 o4 = make_float4(l[j * 4 + 0] * v[j * 4 + 0] * sc,
                                    l[j * 4 + 1] * v[j * 4 + 1] * sc,
                                    l[j * 4 + 2] * v[j * 4 + 2] * sc,
                                    l[j * 4 + 3] * v[j * 4 + 3] * sc);
            *(float4*)(op + j * 4) = o4;
        }
    }
}

// ---------------- launch ----------------
extern "C" void kernel_launch(void* const* d_in, const int* in_sizes, int n_in,
                              void* d_out, int out_size) {
    (void)in_sizes; (void)n_in; (void)out_size;
    const float* Qs = (const float*)d_in[0];
    const float* Ks = (const float*)d_in[1];
    const float* Vs = (const float*)d_in[2];
    const int*   Ql = (const int*)d_in[3];
    const int*   Vl = (const int*)d_in[4];
    const float* WQ = (const float*)d_in[5];
    const float* WK = (const float*)d_in[6];
    const float* WV = (const float*)d_in[7];

    static int smem_set = 0;
    if (!smem_set) {
        cudaFuncSetAttribute(gemm_attn, cudaFuncAttributeMaxDynamicSharedMemorySize,
                             3 * STAGE_B);
        smem_set = 1;
    }

    prep_all<<<XBLOCKS + 6144, 128>>>(Qs, Ks, Vs, Ql, WQ, WK, WV);
    gemm_attn<<<dim3(4, 512), 512, 3 * STAGE_B>>>(Ql, Vl, (float*)d_out);
}

// round 10
// speedup vs baseline: 3.6665x; 1.1049x over previous
#include <cuda_runtime.h>
#include <cuda_fp16.h>
#include <cstdint>

// ---------------- scratch (static __device__, no allocs) ----------------
#define XN (3u*32768u*512u)
#define WN (3u*512u*512u)
__device__ __half g_xhi[XN];
__device__ __half g_xlo[XN];
__device__ __half g_wthi[WN];   // [m][n][k] fp16, K-major (W transposed)
__device__ __half g_wtlo[WN];

__device__ __forceinline__ uint32_t smem_u32(const void* p) {
    uint32_t a;
    asm("{ .reg .u64 t; cvta.to.shared.u64 t, %1; cvt.u32.u64 %0, t; }" : "=r"(a) : "l"(p));
    return a;
}

#define LDSM4(r, a) \
    asm volatile("ldmatrix.sync.aligned.m8n8.x4.shared.b16 {%0,%1,%2,%3}, [%4];" \
        : "=r"((r)[0]), "=r"((r)[1]), "=r"((r)[2]), "=r"((r)[3]) : "r"(a))

#define MMA16816(c, a, b0, b1) \
    asm volatile("mma.sync.aligned.m16n8k16.row.col.f32.f16.f16.f32 " \
        "{%0,%1,%2,%3},{%4,%5,%6,%7},{%8,%9},{%0,%1,%2,%3};" \
        : "+f"((c)[0]), "+f"((c)[1]), "+f"((c)[2]), "+f"((c)[3]) \
        : "r"((a)[0]), "r"((a)[1]), "r"((a)[2]), "r"((a)[3]), "r"(b0), "r"(b1))

#define CPA16(dst, src) \
    asm volatile("cp.async.cg.shared.global [%0], [%1], 16;" :: "r"(dst), "l"(src))
#define CPCOMMIT() asm volatile("cp.async.commit_group;" ::: "memory")
#define CPWAIT(n)  asm volatile("cp.async.wait_group %0;" :: "n"(n) : "memory")

// ---------------- fused prep kernel (256-thread blocks) ----------------
// blocks [0, 49152): X split, 2 rows per block
// blocks [49152, 52224): W transpose+split, 256 elems per block
#define XBLOCKS2 49152
__global__ void __launch_bounds__(256)
prep_all(const float* __restrict__ Qs, const float* __restrict__ Ks,
         const float* __restrict__ Vs, const int* __restrict__ Qlen,
         const float* __restrict__ WQ, const float* __restrict__ WK,
         const float* __restrict__ WV) {
    if (blockIdx.x < XBLOCKS2) {
        int gid = blockIdx.x * 2 + (threadIdx.x >> 7);   // row id in 3*32768
        int tcol = threadIdx.x & 127;
        int m = gid >> 15;
        int gr = gid & 32767;
        int b = gr >> 12, s = gr & 4095;
        int qa = (Qlen[b] + 63) & ~63;
        if (s < qa) {
            const float* X = (m == 0) ? Qs : (m == 1) ? Ks : Vs;
            float4 v = ((const float4*)(X + ((size_t)gr << 9)))[tcol];
            union { __half h[4]; uint2 u; } H, L;
            H.h[0] = __float2half_rn(v.x); L.h[0] = __float2half_rn(v.x - __half2float(H.h[0]));
            H.h[1] = __float2half_rn(v.y); L.h[1] = __float2half_rn(v.y - __half2float(H.h[1]));
            H.h[2] = __float2half_rn(v.z); L.h[2] = __float2half_rn(v.z - __half2float(H.h[2]));
            H.h[3] = __float2half_rn(v.w); L.h[3] = __float2half_rn(v.w - __half2float(H.h[3]));
            size_t o = (((size_t)m << 15) + gr) * 512 + tcol * 4;
            *(uint2*)(g_xhi + o) = H.u;
            if (m < 2) *(uint2*)(g_xlo + o) = L.u;
        }
    } else {
        int idx = (blockIdx.x - XBLOCKS2) * 256 + threadIdx.x;   // 3*512*512, [m][n][k]
        int m = idx >> 18;
        int r = idx & 262143;
        int n = r >> 9, k = r & 511;
        const float* W = (m == 0) ? WQ : (m == 1) ? WK : WV;
        float x = W[(size_t)k * 512 + n];
        __half h = __float2half_rn(x);
        g_wthi[idx] = h;
        if (m < 2) g_wtlo[idx] = __float2half_rn(x - __half2float(h));
    }
}

// ---------------- fused GEMM (HMMA) + softmax epilogue ----------------
// CTA: 64 rows x 1 head (N=64), 256 threads, 8 warps (warp tile 16x32), 2 CTAs/SM.
// Q/K: 3-product fp16 split; V: single fp16 product. V_len column culling.
// K chunks of 32, 2-stage cp.async double buffer. Swizzle: 64B rows, c16 ^= (r>>1)&3.
#define XQHI 0
#define XQLO 4096
#define XKHI 8192
#define XKLO 12288
#define XVHI 16384
#define WQHI 20480
#define WQLO 24576
#define WKHI 28672
#define WKLO 32768
#define WVHI 36864
#define STAGE_B 40960
#define NCHUNK  16
#define ESTR    68               // floats per row in epilogue smem

__global__ void __launch_bounds__(256, 2)
gemm_attn(const int* __restrict__ Qlen, const int* __restrict__ Vlen, float* __restrict__ out) {
    extern __shared__ __align__(16) char dsm[];

    const int h = blockIdx.x;                  // head 0..7 (fastest -> X L2 reuse)
    const int tile = blockIdx.y;               // 0..511
    const int b = tile >> 6;
    const int s0 = (tile & 63) << 6;
    const int tid = threadIdx.x;
    const int qlen = Qlen[b];
    float* outbase = out + ((size_t)(b * 4096 + s0)) * 512 + h * 64;

    if (s0 >= qlen) {                          // whole tile masked: write zeros
        #pragma unroll
        for (int i = 0; i < 4; i++) {
            int lin = tid + i * 256;
            int r = lin >> 4, c4 = lin & 15;
            *(float4*)(outbase + (size_t)r * 512 + c4 * 4) = make_float4(0.f, 0.f, 0.f, 0.f);
        }
        return;
    }

    const int vlen = Vlen[b];
    const int nQK = vlen;                      // head-cols of Q/K needed
    const int nV  = (vlen == 0) ? 64 : vlen;   // head-cols of V needed
    const int nWQK = (nQK + 15) & ~15;         // W rows to load (LDSM coverage)
    const int nWV  = (nV + 15) & ~15;

    const uint32_t sbase = smem_u32(dsm);
    const int lane = tid & 31, wid = tid >> 5;
    const int wm = wid >> 1, wn = wid & 1;     // warp tile: rows 16*wm, cols 32*wn
    const int cbw = wn * 32;                   // col base of this warp

    // ldmatrix logical mapping, swizzled physical address (c16 ^= (r>>1)&3)
    const int rA = wm * 16 + ((lane >> 3) & 1) * 8 + (lane & 7);
    const int cA = (lane >> 4) & 1;
    const int swA = (rA >> 1) & 3;
    const int rB = wn * 32 + ((lane >> 4) & 1) * 8 + (lane & 7);
    const int cB = (lane >> 3) & 1;
    const int swB = (rB >> 1) & 3;
    uint32_t offA[2], offB[2];
    #pragma unroll
    for (int ks = 0; ks < 2; ks++) {
        offA[ks] = (uint32_t)(rA * 64 + (((ks * 2 + cA) ^ swA) << 4));
        offB[ks] = (uint32_t)(rB * 64 + (((ks * 2 + cB) ^ swB) << 4));
    }

    float acc[3][4][4];
    #pragma unroll
    for (int m = 0; m < 3; m++)
        #pragma unroll
        for (int nt = 0; nt < 4; nt++)
            #pragma unroll
            for (int q = 0; q < 4; q++) acc[m][nt][q] = 0.f;

    const size_t xrow = (size_t)(b * 4096 + s0);

    // loader: thread -> row tid>>2 (0..63), 16B-col tid&3; 1 CPA16 per tile
    const int lr = tid >> 2, cc = tid & 3;
    const uint32_t po = (uint32_t)(lr << 6) + ((((uint32_t)cc) ^ ((lr >> 1) & 3)) << 4);

    auto load_stage = [&](int c) {
        const int kk0 = (c & 15) << 5;
        const uint32_t sb = sbase + (c & 1) * STAGE_B;
        const size_t xgQ = ((size_t)(0 << 15) + xrow + lr) * 512 + kk0 + cc * 8;
        const size_t xgK = ((size_t)(1 << 15) + xrow + lr) * 512 + kk0 + cc * 8;
        const size_t xgV = ((size_t)(2 << 15) + xrow + lr) * 512 + kk0 + cc * 8;
        const size_t wgQ = ((size_t)(0 * 512 + h * 64 + lr)) * 512 + kk0 + cc * 8;
        const size_t wgK = ((size_t)(1 * 512 + h * 64 + lr)) * 512 + kk0 + cc * 8;
        const size_t wgV = ((size_t)(2 * 512 + h * 64 + lr)) * 512 + kk0 + cc * 8;
        if (nQK > 0) {
            CPA16(sb + XQHI + po, g_xhi + xgQ);
            CPA16(sb + XQLO + po, g_xlo + xgQ);
            CPA16(sb + XKHI + po, g_xhi + xgK);
            CPA16(sb + XKLO + po, g_xlo + xgK);
        }
        CPA16(sb + XVHI + po, g_xhi + xgV);
        if (lr < nWQK) {
            CPA16(sb + WQHI + po, g_wthi + wgQ);
            CPA16(sb + WQLO + po, g_wtlo + wgQ);
            CPA16(sb + WKHI + po, g_wthi + wgK);
            CPA16(sb + WKLO + po, g_wtlo + wgK);
        }
        if (lr < nWV) CPA16(sb + WVHI + po, g_wthi + wgV);
        CPCOMMIT();
    };

    auto compute = [&](int c) {
        const uint32_t sb = sbase + (c & 1) * STAGE_B;
        #pragma unroll
        for (int ks = 0; ks < 2; ks++) {
            uint32_t aH[4], aL[4], bH[2][4], bL[2][4];
            if (cbw < nQK) {
                // ---- Q: 3 products ----
                LDSM4(aH, sb + XQHI + offA[ks]);
                LDSM4(aL, sb + XQLO + offA[ks]);
                LDSM4(bH[0], sb + WQHI + offB[ks]);
                LDSM4(bL[0], sb + WQLO + offB[ks]);
                if (cbw + 16 < nQK) {
                    LDSM4(bH[1], sb + WQHI + offB[ks] + 1024);
                    LDSM4(bL[1], sb + WQLO + offB[ks] + 1024);
                }
                #pragma unroll
                for (int nt = 0; nt < 4; nt++) {
                    if (cbw + nt * 8 < nQK) {
                        const int nb = nt >> 1, p = (nt & 1) * 2;
                        MMA16816(acc[0][nt], aH, bH[nb][p], bH[nb][p + 1]);
                        MMA16816(acc[0][nt], aH, bL[nb][p], bL[nb][p + 1]);
                        MMA16816(acc[0][nt], aL, bH[nb][p], bH[nb][p + 1]);
                    }
                }
                // ---- K: 3 products ----
                LDSM4(aH, sb + XKHI + offA[ks]);
                LDSM4(aL, sb + XKLO + offA[ks]);
                LDSM4(bH[0], sb + WKHI + offB[ks]);
                LDSM4(bL[0], sb + WKLO + offB[ks]);
                if (cbw + 16 < nQK) {
                    LDSM4(bH[1], sb + WKHI + offB[ks] + 1024);
                    LDSM4(bL[1], sb + WKLO + offB[ks] + 1024);
                }
                #pragma unroll
                for (int nt = 0; nt < 4; nt++) {
                    if (cbw + nt * 8 < nQK) {
                        const int nb = nt >> 1, p = (nt & 1) * 2;
                        MMA16816(acc[1][nt], aH, bH[nb][p], bH[nb][p + 1]);
                        MMA16816(acc[1][nt], aH, bL[nb][p], bL[nb][p + 1]);
                        MMA16816(acc[1][nt], aL, bH[nb][p], bH[nb][p + 1]);
                    }
                }
            }
            // ---- V: single product ----
            if (cbw < nV) {
                LDSM4(aH, sb + XVHI + offA[ks]);
                LDSM4(bH[0], sb + WVHI + offB[ks]);
                if (cbw + 16 < nV) LDSM4(bH[1], sb + WVHI + offB[ks] + 1024);
                #pragma unroll
                for (int nt = 0; nt < 4; nt++) {
                    if (cbw + nt * 8 < nV) {
                        const int nb = nt >> 1, p = (nt & 1) * 2;
                        MMA16816(acc[2][nt], aH, bH[nb][p], bH[nb][p + 1]);
                    }
                }
            }
        }
    };

    load_stage(0);
    load_stage(1);
    for (int c = 0; c < NCHUNK; c++) {
        if (c < NCHUNK - 1) { CPWAIT(1); } else { CPWAIT(0); }
        __syncthreads();
        compute(c);
        __syncthreads();
        if (c + 2 < NCHUNK) load_stage(c + 2);
    }

    // ---- epilogue: dump accs to smem (reuse tile buffers), per-row softmax ----
    {
        float* sepi = (float*)dsm;
        const int g = lane >> 2, t = lane & 3;
        #pragma unroll
        for (int m = 0; m < 3; m++)
            #pragma unroll
            for (int nt = 0; nt < 4; nt++) {
                float* p = sepi + (size_t)((m * 64 + wm * 16 + g) * ESTR
                                           + wn * 32 + nt * 8 + 2 * t);
                p[0] = acc[m][nt][0];
                p[1] = acc[m][nt][1];
                p[8 * ESTR]     = acc[m][nt][2];
                p[8 * ESTR + 1] = acc[m][nt][3];
            }
        __syncthreads();

        const int row = tid >> 2, qd = tid & 3;    // thread = (row, 16-col quarter)
        float q[16], k[16], v[16];
        #pragma unroll
        for (int j = 0; j < 4; j++) {
            *(float4*)&q[j * 4] = *(float4*)&sepi[(0 * 64 + row) * ESTR + qd * 16 + j * 4];
            *(float4*)&k[j * 4] = *(float4*)&sepi[(1 * 64 + row) * ESTR + qd * 16 + j * 4];
            *(float4*)&v[j * 4] = *(float4*)&sepi[(2 * 64 + row) * ESTR + qd * 16 + j * 4];
        }
        float l[16];
        #pragma unroll
        for (int j = 0; j < 16; j++) {
            l[j] = q[j] * k[j] * 0.125f;
            if (qd * 16 + j >= vlen) l[j] -= 1e12f;
        }
        float mx = l[0];
        #pragma unroll
        for (int j = 1; j < 16; j++) mx = fmaxf(mx, l[j]);
        mx = fmaxf(mx, __shfl_xor_sync(0xffffffffu, mx, 1));
        mx = fmaxf(mx, __shfl_xor_sync(0xffffffffu, mx, 2));
        float sum = 0.f;
        #pragma unroll
        for (int j = 0; j < 16; j++) { l[j] = expf(l[j] - mx); sum += l[j]; }
        sum += __shfl_xor_sync(0xffffffffu, sum, 1);
        sum += __shfl_xor_sync(0xffffffffu, sum, 2);
        float sc = 1.0f / sum;
        if (s0 + row >= qlen) sc = 0.f;        // qmask
        float* op = outbase + (size_t)row * 512 + qd * 16;
        #pragma unroll
        for (int j = 0; j < 4; j++) {
            float4 o4 = make_float4(l[j * 4 + 0] * v[j * 4 + 0] * sc,
                                    l[j * 4 + 1] * v[j * 4 + 1] * sc,
                                    l[j * 4 + 2] * v[j * 4 + 2] * sc,
                                    l[j * 4 + 3] * v[j * 4 + 3] * sc);
            *(float4*)(op + j * 4) = o4;
        }
    }
}

// ---------------- launch ----------------
extern "C" void kernel_launch(void* const* d_in, const int* in_sizes, int n_in,
                              void* d_out, int out_size) {
    (void)in_sizes; (void)n_in; (void)out_size;
    const float* Qs = (const float*)d_in[0];
    const float* Ks = (const float*)d_in[1];
    const float* Vs = (const float*)d_in[2];
    const int*   Ql = (const int*)d_in[3];
    const int*   Vl = (const int*)d_in[4];
    const float* WQ = (const float*)d_in[5];
    const float* WK = (const float*)d_in[6];
    const float* WV = (const float*)d_in[7];

    static int smem_set = 0;
    if (!smem_set) {
        cudaFuncSetAttribute(gemm_attn, cudaFuncAttributeMaxDynamicSharedMemorySize,
                             2 * STAGE_B);
        smem_set = 1;
    }

    prep_all<<<XBLOCKS2 + 3072, 256>>>(Qs, Ks, Vs, Ql, WQ, WK, WV);
    gemm_attn<<<dim3(8, 512), 256, 2 * STAGE_B>>>(Ql, Vl, (float*)d_out);
}